// round 11
// baseline (speedup 1.0000x reference)
#include <cuda_runtime.h>
#include <cstdint>

// ExtractLearnableSlices — TMA bulk-copy loads (bypass L1tex queue), direct
// smem epilogue. One head x 4 batches per block.
//   x: (B=64, C=64, L=16384) f32
//   channel_params/offset_params: (128,) f32
//   out: (B=64, N=128, W=512) f32
//
// cp.async.bulk copies the raw 520-float windows (both channels, 4 batches)
// into smem; one mbarrier (expect_tx = full 16640 B). Epilogue: per j
// (j = tid + k*128) compute pos/pf/wt/idx once (exact ref f32 math), then per
// batch fuse channel lerp + time lerp from raw smem. No LDG window traffic,
// no staging pass, conflict-free LDS, coalesced STG.

#define B_DIM   64
#define C_DIM   64
#define L_DIM   16384
#define N_HEADS 128
#define WIDTH   512
#define THREADS 128
#define NB      4
#define WIN     520                 // floats per window
#define WIN_B   (WIN * 4)           // 2080 bytes, multiple of 16

__global__ __launch_bounds__(THREADS) void extract_slices_kernel(
    const float* __restrict__ x,
    const float* __restrict__ channel_params,
    const float* __restrict__ offset_params,
    float* __restrict__ out)
{
    // win[bb][0] = floor-channel window, win[bb][1] = ceil-channel window
    __shared__ __align__(16) float win[NB][2][WIN];
    __shared__ __align__(8) uint64_t mbar;

    const int tid = threadIdx.x;        // 0..127
    const int i   = blockIdx.x;         // head
    const int b0  = blockIdx.y * NB;    // first batch

    uint32_t mbar_addr;
    {
        uint64_t tmp;
        asm("cvta.to.shared.u64 %0, %1;" : "=l"(tmp) : "l"(&mbar));
        mbar_addr = (uint32_t)tmp;
    }

    if (tid == 0) {
        asm volatile("mbarrier.init.shared.b64 [%0], 1;" :: "r"(mbar_addr) : "memory");
    }
    __syncthreads();

    // ---- per-head params (exact same math as all passing rounds) ----
    const float cp = __ldg(&channel_params[i]);
    const float op = __ldg(&offset_params[i]);

    const float sc      = 1.0f / (1.0f + expf(-cp));
    const float desired = sc * (float)(C_DIM - 1);   // > 0
    const int   fc      = (int)desired;              // floor (positive)
    const int   cc      = min(fc + 1, C_DIM - 1);
    const float wc      = desired - (float)fc;

    const float so  = 1.0f / (1.0f + expf(-op));
    const float t0  = so * (float)(L_DIM - WIDTH);   // > 0
    const int   pf0 = (int)t0;                       // floor (positive)
    const int   l0  = (pf0 - 1) & ~3;                // float4-aligned (16B) origin

    const int xfo = fc * L_DIM + l0;
    const int xco = cc * L_DIM + l0;

    // ---- issue 8 bulk copies from one thread ----
    if (tid == 0) {
        asm volatile("mbarrier.arrive.expect_tx.shared.b64 _, [%0], %1;"
                     :: "r"(mbar_addr), "r"((uint32_t)(NB * 2 * WIN_B)) : "memory");
        #pragma unroll
        for (int bb = 0; bb < NB; ++bb) {
            const size_t base = (size_t)(b0 + bb) * (size_t)(C_DIM * L_DIM);
            const float* srcf = x + base + xfo;
            const float* srcc = x + base + xco;
            uint64_t df, dc;
            asm("cvta.to.shared.u64 %0, %1;" : "=l"(df) : "l"(&win[bb][0][0]));
            asm("cvta.to.shared.u64 %0, %1;" : "=l"(dc) : "l"(&win[bb][1][0]));
            asm volatile(
                "cp.async.bulk.shared::cta.global.mbarrier::complete_tx::bytes "
                "[%0], [%1], %2, [%3];"
                :: "r"((uint32_t)df), "l"(srcf), "r"((uint32_t)WIN_B), "r"(mbar_addr)
                : "memory");
            asm volatile(
                "cp.async.bulk.shared::cta.global.mbarrier::complete_tx::bytes "
                "[%0], [%1], %2, [%3];"
                :: "r"((uint32_t)dc), "l"(srcc), "r"((uint32_t)WIN_B), "r"(mbar_addr)
                : "memory");
        }
    }

    // ---- wait for all windows (acquire orders TMA writes before LDS) ----
    {
        uint32_t done;
        asm volatile(
            "{\n\t"
            ".reg .pred p;\n\t"
            "mbarrier.try_wait.parity.acquire.cta.shared::cta.b64 p, [%1], 0;\n\t"
            "selp.b32 %0, 1, 0, p;\n\t"
            "}" : "=r"(done) : "r"(mbar_addr) : "memory");
        while (!done) {
            asm volatile(
                "{\n\t"
                ".reg .pred p;\n\t"
                "mbarrier.try_wait.parity.acquire.cta.shared::cta.b64 p, [%1], 0, 0x989680;\n\t"
                "selp.b32 %0, 1, 0, p;\n\t"
                "}" : "=r"(done) : "r"(mbar_addr) : "memory");
        }
    }

    // ---- epilogue: idx/wt once per j, reuse across 4 batches ----
    const size_t ostride = (size_t)N_HEADS * WIDTH;
    float* __restrict__ obase = out + ((size_t)b0 * N_HEADS + i) * WIDTH + tid;

    #pragma unroll
    for (int k = 0; k < 4; ++k) {
        const int   j   = tid + k * THREADS;
        const float pos = t0 + (float)j;       // exact ref f32 math
        const int   pf  = (int)pos;            // floor (positive)
        const float wt  = pos - (float)pf;
        const int   idx = pf - l0;             // in [0, 517]

        float* __restrict__ o = obase + k * THREADS;
        #pragma unroll
        for (int bb = 0; bb < NB; ++bb) {
            const float a0 = win[bb][0][idx];
            const float a1 = win[bb][0][idx + 1];
            const float c0 = win[bb][1][idx];
            const float c1 = win[bb][1][idx + 1];
            const float v0 = a0 + wc * (c0 - a0);
            const float v1 = a1 + wc * (c1 - a1);
            o[bb * ostride] = v0 + wt * (v1 - v0);
        }
    }
}

extern "C" void kernel_launch(void* const* d_in, const int* in_sizes, int n_in,
                              void* d_out, int out_size)
{
    const float* x  = (const float*)d_in[0];
    const float* ch = (const float*)d_in[1];
    const float* of = (const float*)d_in[2];
    float* out = (float*)d_out;

    dim3 grid(N_HEADS, B_DIM / NB);
    extract_slices_kernel<<<grid, THREADS>>>(x, ch, of, out);
}